// round 2
// baseline (speedup 1.0000x reference)
#include <cuda_runtime.h>
#include <cuda_bf16.h>
#include <math.h>

#define Bb 128
#define Pp 196
#define Ee 2048
#define Hh 512
#define Vv 10000
#define Tt 20
#define TS 19
#define G4 2048
#define NCAT 4608
#define NINIT 1024

// ---------------- static device scratch (no allocs allowed) ----------------
__device__ float d_Ws[Bb * Pp * Hh];        // [B,P,H] precomputed attention proj
__device__ float d_avg[Bb * Ee];
__device__ float d_h[Bb * Hh];
__device__ float d_c[Bb * Hh];
__device__ float d_hcat[Bb * NCAT];         // [hU(512) | gate(2048) | hUl(2048)]
__device__ float d_alpha[Bb * Pp];
__device__ float d_gctx[Bb * Ee];
__device__ float d_embMat[TS * Bb * Hh];
__device__ float d_embWl[TS * Bb * G4];     // emb @ Wl_top, all steps
__device__ float d_Wcat[Hh * NCAT];         // [U_att | Wfb | Ul] concat
__device__ float d_WcatI[Ee * NINIT];       // [Wih | Wic] concat
__device__ float d_part[5120000];           // split-K partials (max 4*128*10000)

__device__ __forceinline__ float sigf(float x) { return 1.0f / (1.0f + expf(-x)); }

// ---------------- weight concat builders ----------------
__global__ void buildWcatKer(const float* __restrict__ U_att,
                             const float* __restrict__ Wfb,
                             const float* __restrict__ Ul) {
    int i = blockIdx.x * 256 + threadIdx.x;
    if (i >= Hh * NCAT) return;
    int r = i / NCAT, c = i % NCAT;
    float v;
    if (c < 512)       v = U_att[r * Hh + c];
    else if (c < 2560) v = Wfb[r * Ee + (c - 512)];
    else               v = Ul[r * G4 + (c - 2560)];
    d_Wcat[i] = v;
}

__global__ void buildWcatIKer(const float* __restrict__ Wih,
                              const float* __restrict__ Wic) {
    int i = blockIdx.x * 256 + threadIdx.x;
    if (i >= Ee * NINIT) return;
    int r = i / NINIT, c = i % NINIT;
    d_WcatI[i] = (c < 512) ? Wih[r * Hh + c] : Wic[r * Hh + (c - 512)];
}

// ---------------- mean over patches ----------------
__global__ void avgKer(const float* __restrict__ F) {
    int b = blockIdx.y;
    int e = blockIdx.x * 256 + threadIdx.x;
    const float* f = F + (size_t)b * Pp * Ee + e;
    float s = 0.f;
#pragma unroll 7
    for (int p = 0; p < Pp; p++) s += f[(size_t)p * Ee];
    d_avg[b * Ee + e] = s * (1.0f / Pp);
}

// ---------------- embedding gather ----------------
__global__ void embGatherKer(const int* __restrict__ cap, const float* __restrict__ Wemb) {
    int i = blockIdx.x * 256 + threadIdx.x;
    if (i >= TS * Bb * Hh) return;
    int h = i % Hh;
    int r = i / Hh;
    int t = r / Bb;
    int b = r % Bb;
    int tok = cap[b * Tt + t];
    d_embMat[i] = Wemb[(size_t)tok * Hh + h];
}

// ---------------- large tiled SGEMM: C[M,N] = A[M,K] @ B[K,N] (+bias) ----------------
// BM=BN=128, BK=8, 256 threads, 8x8 per thread. Requires M%128==0, N%128==0, K%8==0.
__global__ void __launch_bounds__(256) sgemm128(const float* __restrict__ A,
                                                const float* __restrict__ Bw,
                                                float* __restrict__ C,
                                                int M, int N, int K,
                                                const float* __restrict__ bias) {
    __shared__ __align__(16) float As[8][132];
    __shared__ __align__(16) float Bs[8][132];
    int t = threadIdx.x;
    int n0 = blockIdx.x * 128, m0 = blockIdx.y * 128;
    int arow = t >> 1, akq = (t & 1) * 4;
    int bkr = t >> 5, bnq = (t & 31) * 4;
    int ty = t >> 4, tx = t & 15;
    float acc[8][8];
#pragma unroll
    for (int i = 0; i < 8; i++)
#pragma unroll
        for (int j = 0; j < 8; j++) acc[i][j] = 0.f;

    for (int k0 = 0; k0 < K; k0 += 8) {
        float4 av = *(const float4*)(A + (size_t)(m0 + arow) * K + k0 + akq);
        float4 bv = *(const float4*)(Bw + (size_t)(k0 + bkr) * N + n0 + bnq);
        __syncthreads();
        As[akq + 0][arow] = av.x;
        As[akq + 1][arow] = av.y;
        As[akq + 2][arow] = av.z;
        As[akq + 3][arow] = av.w;
        *(float4*)&Bs[bkr][bnq] = bv;
        __syncthreads();
#pragma unroll
        for (int kk = 0; kk < 8; kk++) {
            float4 a0 = *(const float4*)&As[kk][ty * 8];
            float4 a1 = *(const float4*)&As[kk][ty * 8 + 4];
            float4 b0 = *(const float4*)&Bs[kk][tx * 8];
            float4 b1 = *(const float4*)&Bs[kk][tx * 8 + 4];
            float a[8] = {a0.x, a0.y, a0.z, a0.w, a1.x, a1.y, a1.z, a1.w};
            float b[8] = {b0.x, b0.y, b0.z, b0.w, b1.x, b1.y, b1.z, b1.w};
#pragma unroll
            for (int i = 0; i < 8; i++)
#pragma unroll
                for (int j = 0; j < 8; j++) acc[i][j] += a[i] * b[j];
        }
    }
#pragma unroll
    for (int i = 0; i < 8; i++) {
        size_t row = (size_t)(m0 + ty * 8 + i) * N + n0 + tx * 8;
#pragma unroll
        for (int j = 0; j < 8; j++) {
            float v = acc[i][j];
            if (bias) v += bias[n0 + tx * 8 + j];
            C[row + j] = v;
        }
    }
}

// ---------------- skinny GEMM (M=128) with split-K partials ----------------
// part[ks][128][N] = A[128, kchunk] @ W[kchunk, N].  grid = (ceil(N/64), KS).
// Requires kchunk%16==0, N%4==0, lda == K.
__global__ void __launch_bounds__(256) skinnyGemm(const float* __restrict__ A,
                                                  const float* __restrict__ W,
                                                  float* __restrict__ part,
                                                  int K, int N, int ldw, int kchunk) {
    __shared__ __align__(16) float As[16][132];
    __shared__ __align__(16) float Wsm[16][68];
    int t = threadIdx.x;
    int n0 = blockIdx.x * 64;
    int ks = blockIdx.y;
    int kbeg = ks * kchunk;
    int kend = kbeg + kchunk;
    int arow = t >> 1, akq = (t & 1) * 8;
    int wkr = t >> 4, wnq = (t & 15) * 4;
    int rg = t >> 4, cg = t & 15;
    float acc[8][4];
#pragma unroll
    for (int i = 0; i < 8; i++)
#pragma unroll
        for (int j = 0; j < 4; j++) acc[i][j] = 0.f;

    for (int k0 = kbeg; k0 < kend; k0 += 16) {
        float4 a0 = *(const float4*)(A + (size_t)arow * K + k0 + akq);
        float4 a1 = *(const float4*)(A + (size_t)arow * K + k0 + akq + 4);
        float4 wv = make_float4(0.f, 0.f, 0.f, 0.f);
        if (n0 + wnq < N) wv = *(const float4*)(W + (size_t)(k0 + wkr) * ldw + n0 + wnq);
        __syncthreads();
        As[akq + 0][arow] = a0.x;
        As[akq + 1][arow] = a0.y;
        As[akq + 2][arow] = a0.z;
        As[akq + 3][arow] = a0.w;
        As[akq + 4][arow] = a1.x;
        As[akq + 5][arow] = a1.y;
        As[akq + 6][arow] = a1.z;
        As[akq + 7][arow] = a1.w;
        *(float4*)&Wsm[wkr][wnq] = wv;
        __syncthreads();
#pragma unroll
        for (int kk = 0; kk < 16; kk++) {
            float4 aa0 = *(const float4*)&As[kk][rg * 8];
            float4 aa1 = *(const float4*)&As[kk][rg * 8 + 4];
            float4 ww = *(const float4*)&Wsm[kk][cg * 4];
            float a[8] = {aa0.x, aa0.y, aa0.z, aa0.w, aa1.x, aa1.y, aa1.z, aa1.w};
            float w[4] = {ww.x, ww.y, ww.z, ww.w};
#pragma unroll
            for (int i = 0; i < 8; i++)
#pragma unroll
                for (int j = 0; j < 4; j++) acc[i][j] += a[i] * w[j];
        }
    }
    if (n0 + cg * 4 < N) {
        float* base = part + (size_t)ks * Bb * N + n0 + cg * 4;
#pragma unroll
        for (int i = 0; i < 8; i++) {
            float4 v = make_float4(acc[i][0], acc[i][1], acc[i][2], acc[i][3]);
            *(float4*)(base + (size_t)(rg * 8 + i) * N) = v;
        }
    }
}

// ---------------- epilogues ----------------
__global__ void epiInitKer(int KS, const float* __restrict__ bih, const float* __restrict__ bic) {
    int i = blockIdx.x * 256 + threadIdx.x;
    if (i >= Bb * NINIT) return;
    int m = i / NINIT, n = i % NINIT;
    float s = 0.f;
    for (int ks = 0; ks < KS; ks++) s += d_part[(size_t)ks * Bb * NINIT + i];
    if (n < 512) d_h[m * Hh + n] = tanhf(s + bih[n]);
    else         d_c[m * Hh + (n - 512)] = tanhf(s + bic[n - 512]);
}

__global__ void epiHcatKer(int KS, const float* __restrict__ bU, const float* __restrict__ bfb) {
    int i = blockIdx.x * 256 + threadIdx.x;
    if (i >= Bb * NCAT) return;
    int n = i % NCAT;
    float s = 0.f;
    for (int ks = 0; ks < KS; ks++) s += d_part[(size_t)ks * Bb * NCAT + i];
    if (n < 512)       s += bU[n];
    else if (n < 2560) s = sigf(s + bfb[n - 512]);
    d_hcat[i] = s;
}

__global__ void epiPredsKer(int KS, const float* __restrict__ bdo,
                            float* __restrict__ outp, int t) {
    int i = blockIdx.x * 256 + threadIdx.x;
    if (i >= Bb * Vv) return;
    int m = i / Vv, n = i % Vv;
    float s = bdo[n];
    for (int ks = 0; ks < KS; ks++) s += d_part[(size_t)ks * Bb * Vv + i];
    outp[(size_t)m * TS * Vv + (size_t)t * Vv + n] = s;
}

__global__ void lstmFusedKer(int KS, const float* __restrict__ embWl_t,
                             const float* __restrict__ bl) {
    int i = blockIdx.x * 256 + threadIdx.x;
    if (i >= Bb * Hh) return;
    int m = i / Hh, n = i % Hh;
    float g[4];
#pragma unroll
    for (int j = 0; j < 4; j++) {
        int col = j * Hh + n;
        float s = bl[col] + embWl_t[m * G4 + col] + d_hcat[m * NCAT + 2560 + col];
        for (int ks = 0; ks < KS; ks++) s += d_part[(size_t)ks * Bb * G4 + m * G4 + col];
        g[j] = s;
    }
    float ig = sigf(g[0]);
    float fg = sigf(g[1]);
    float gg = tanhf(g[2]);
    float og = sigf(g[3]);
    float cc = fg * d_c[i] + ig * gg;
    d_c[i] = cc;
    d_h[i] = og * tanhf(cc);
}

// ---------------- attention scores + softmax ----------------
__global__ void __launch_bounds__(256) attKer(const float* __restrict__ v_att,
                                              float* __restrict__ alphasOut, int t) {
    int b = blockIdx.x, tid = threadIdx.x;
    __shared__ float hU[512];
    __shared__ float vv[512];
    __shared__ float e_sm[Pp];
    __shared__ float red[256];
    hU[tid] = d_hcat[b * NCAT + tid];
    hU[tid + 256] = d_hcat[b * NCAT + tid + 256];
    vv[tid] = v_att[tid];
    vv[tid + 256] = v_att[tid + 256];
    __syncthreads();
    int w = tid >> 5, lane = tid & 31;
    for (int p = w; p < Pp; p += 8) {
        const float* ws = d_Ws + (size_t)(b * Pp + p) * Hh;
        float s = 0.f;
#pragma unroll
        for (int i = 0; i < 16; i++) {
            int hh = lane + 32 * i;
            s += tanhf(ws[hh] + hU[hh]) * vv[hh];
        }
#pragma unroll
        for (int o = 16; o; o >>= 1) s += __shfl_xor_sync(0xffffffffu, s, o);
        if (lane == 0) e_sm[p] = s;
    }
    __syncthreads();
    float mx = -1e30f;
    for (int p = tid; p < Pp; p += 256) mx = fmaxf(mx, e_sm[p]);
    red[tid] = mx;
    __syncthreads();
    for (int s2 = 128; s2 > 0; s2 >>= 1) {
        if (tid < s2) red[tid] = fmaxf(red[tid], red[tid + s2]);
        __syncthreads();
    }
    mx = red[0];
    __syncthreads();
    float sum = 0.f;
    for (int p = tid; p < Pp; p += 256) sum += expf(e_sm[p] - mx);
    red[tid] = sum;
    __syncthreads();
    for (int s2 = 128; s2 > 0; s2 >>= 1) {
        if (tid < s2) red[tid] += red[tid + s2];
        __syncthreads();
    }
    float inv = 1.0f / red[0];
    for (int p = tid; p < Pp; p += 256) {
        float a = expf(e_sm[p] - mx) * inv;
        d_alpha[b * Pp + p] = a;
        alphasOut[((size_t)b * TS + t) * Pp + p] = a;
    }
}

// ---------------- context = alpha @ F, gated ----------------
__global__ void __launch_bounds__(256) ctxKer(const float* __restrict__ F) {
    int b = blockIdx.y;
    int e = blockIdx.x * 256 + threadIdx.x;
    __shared__ float al[Pp];
    if (threadIdx.x < Pp) al[threadIdx.x] = d_alpha[b * Pp + threadIdx.x];
    __syncthreads();
    const float* f = F + (size_t)b * Pp * Ee + e;
    float s = 0.f;
#pragma unroll 7
    for (int p = 0; p < Pp; p++) s += al[p] * f[(size_t)p * Ee];
    float gate = d_hcat[b * NCAT + 512 + e];
    d_gctx[b * Ee + e] = s * gate;
}

// ---------------- host ----------------
extern "C" void kernel_launch(void* const* d_in, const int* in_sizes, int n_in,
                              void* d_out, int out_size) {
    const float* F      = (const float*)d_in[0];
    const int*   cap    = (const int*)d_in[1];
    const float* U_att  = (const float*)d_in[2];
    const float* bU_att = (const float*)d_in[3];
    const float* W_att  = (const float*)d_in[4];
    const float* bW_att = (const float*)d_in[5];
    const float* v_att  = (const float*)d_in[6];
    // d_in[7] = bv_att: constant shift before softmax — cancels exactly, unused.
    const float* Wih    = (const float*)d_in[8];
    const float* bih    = (const float*)d_in[9];
    const float* Wic    = (const float*)d_in[10];
    const float* bic    = (const float*)d_in[11];
    const float* Wfb    = (const float*)d_in[12];
    const float* bfb    = (const float*)d_in[13];
    const float* Wdo    = (const float*)d_in[14];
    const float* bdo    = (const float*)d_in[15];
    const float* Wemb   = (const float*)d_in[16];
    const float* Wl     = (const float*)d_in[17];
    const float* Ul     = (const float*)d_in[18];
    const float* bl     = (const float*)d_in[19];

    float* outp = (float*)d_out;
    float* alphasOut = outp + (size_t)Bb * TS * Vv;

    float *pPart, *pWcat, *pWcatI, *pAvg, *pH, *pGctx, *pEmbMat, *pEmbWl, *pWs;
    cudaGetSymbolAddress((void**)&pPart, d_part);
    cudaGetSymbolAddress((void**)&pWcat, d_Wcat);
    cudaGetSymbolAddress((void**)&pWcatI, d_WcatI);
    cudaGetSymbolAddress((void**)&pAvg, d_avg);
    cudaGetSymbolAddress((void**)&pH, d_h);
    cudaGetSymbolAddress((void**)&pGctx, d_gctx);
    cudaGetSymbolAddress((void**)&pEmbMat, d_embMat);
    cudaGetSymbolAddress((void**)&pEmbWl, d_embWl);
    cudaGetSymbolAddress((void**)&pWs, d_Ws);

    // ---- precompute ----
    buildWcatKer<<<(Hh * NCAT) / 256, 256>>>(U_att, Wfb, Ul);
    buildWcatIKer<<<(Ee * NINIT) / 256, 256>>>(Wih, Wic);
    avgKer<<<dim3(Ee / 256, Bb), 256>>>(F);
    // init state: [128,1024] = avg[128,2048] @ WcatI[2048,1024], split-K 8
    skinnyGemm<<<dim3(NINIT / 64, 8), 256>>>(pAvg, pWcatI, pPart, Ee, NINIT, NINIT, Ee / 8);
    epiInitKer<<<(Bb * NINIT) / 256, 256>>>(8, bih, bic);
    // W_s = F2d[25088,2048] @ W_att[2048,512] + bW
    sgemm128<<<dim3(Hh / 128, (Bb * Pp) / 128), 256>>>(F, W_att, pWs, Bb * Pp, Hh, Ee, bW_att);
    // embeddings (all steps) then embWl = emb @ Wl_top
    embGatherKer<<<(TS * Bb * Hh) / 256, 256>>>(cap, Wemb);
    sgemm128<<<dim3(G4 / 128, (TS * Bb) / 128), 256>>>(pEmbMat, Wl, pEmbWl, TS * Bb, G4, Hh, nullptr);

    // ---- sequential decode ----
    for (int t = 0; t < TS; t++) {
        // h @ [U_att | Wfb | Ul]  (K=512, N=4608), split-K 4
        skinnyGemm<<<dim3(NCAT / 64, 4), 256>>>(pH, pWcat, pPart, Hh, NCAT, NCAT, Hh / 4);
        epiHcatKer<<<(Bb * NCAT) / 256, 256>>>(4, bU_att, bfb);
        // attention scores + softmax -> alpha (also writes alphas output)
        attKer<<<Bb, 256>>>(v_att, alphasOut, t);
        // gated context
        ctxKer<<<dim3(Ee / 256, Bb), 256>>>(F);
        // gates partial: gctx[128,2048] @ Wl_bot[2048,2048], split-K 8
        skinnyGemm<<<dim3(G4 / 64, 8), 256>>>(pGctx, Wl + (size_t)Hh * G4, pPart, Ee, G4, G4, Ee / 8);
        // LSTM pointwise (sums partials + embWl_t + hUl + bl)
        lstmFusedKer<<<(Bb * Hh) / 256, 256>>>(8, pEmbWl + (size_t)t * Bb * G4, bl);
        // preds: h_new[128,512] @ Wdo[512,10000], split-K 4
        skinnyGemm<<<dim3((Vv + 63) / 64, 4), 256>>>(pH, Wdo, pPart, Hh, Vv, Vv, Hh / 4);
        epiPredsKer<<<(Bb * Vv) / 256, 256>>>(4, bdo, outp, t);
    }
}

// round 4
// speedup vs baseline: 1.0550x; 1.0550x over previous
#include <cuda_runtime.h>
#include <cuda_bf16.h>
#include <math.h>
#include <stdint.h>

#define Bb 128
#define Pp 196
#define Ee 2048
#define Hh 512
#define Vv 10000
#define Tt 20
#define TS 19
#define G4 2048
#define NCAT 4608
#define NINIT 1024

// ---------------- static device scratch ----------------
__device__ float d_Ws[Bb * Pp * Hh];
__device__ float d_avg[Bb * Ee];
__device__ float d_h[Bb * Hh];
__device__ float d_c[Bb * Hh];
__device__ float d_hcat[Bb * NCAT];         // [hU(512) | gate(2048) | hUl(2048)]
__device__ float d_alpha[Bb * Pp];
__device__ float d_gctx[Bb * Ee];
__device__ float d_embMat[TS * Bb * Hh];
__device__ float d_embWl[TS * Bb * G4];
__device__ float d_Wcat[Hh * NCAT];
__device__ float d_WcatI[Ee * NINIT];
__device__ float d_part[5120000];           // split-K partials (max 4*128*10000)

__device__ __forceinline__ float sigf(float x) { return 1.0f / (1.0f + expf(-x)); }

__device__ __forceinline__ void split_tf32(float x, uint32_t& hi, uint32_t& lo) {
    uint32_t h;
    asm("cvt.rna.tf32.f32 %0, %1;" : "=r"(h) : "f"(x));
    float l = x - __uint_as_float(h);
    uint32_t lb;
    asm("cvt.rna.tf32.f32 %0, %1;" : "=r"(lb) : "f"(l));
    hi = h; lo = lb;
}

__device__ __forceinline__ void mma_tf32(float* d, const uint32_t* a, const uint32_t* b) {
    asm volatile(
        "mma.sync.aligned.m16n8k8.row.col.f32.tf32.tf32.f32 "
        "{%0,%1,%2,%3}, {%4,%5,%6,%7}, {%8,%9}, {%0,%1,%2,%3};"
        : "+f"(d[0]), "+f"(d[1]), "+f"(d[2]), "+f"(d[3])
        : "r"(a[0]), "r"(a[1]), "r"(a[2]), "r"(a[3]), "r"(b[0]), "r"(b[1]));
}

// ---------------- weight concat builders ----------------
__global__ void buildWcatKer(const float* __restrict__ U_att,
                             const float* __restrict__ Wfb,
                             const float* __restrict__ Ul) {
    int i = blockIdx.x * 256 + threadIdx.x;
    if (i >= Hh * NCAT) return;
    int r = i / NCAT, c = i % NCAT;
    float v;
    if (c < 512)       v = U_att[r * Hh + c];
    else if (c < 2560) v = Wfb[r * Ee + (c - 512)];
    else               v = Ul[r * G4 + (c - 2560)];
    d_Wcat[i] = v;
}

__global__ void buildWcatIKer(const float* __restrict__ Wih,
                              const float* __restrict__ Wic) {
    int i = blockIdx.x * 256 + threadIdx.x;
    if (i >= Ee * NINIT) return;
    int r = i / NINIT, c = i % NINIT;
    d_WcatI[i] = (c < 512) ? Wih[r * Hh + c] : Wic[r * Hh + (c - 512)];
}

// ---------------- mean over patches ----------------
__global__ void avgKer(const float* __restrict__ F) {
    int b = blockIdx.y;
    int e = blockIdx.x * 256 + threadIdx.x;
    const float* f = F + (size_t)b * Pp * Ee + e;
    float s = 0.f;
#pragma unroll 7
    for (int p = 0; p < Pp; p++) s += f[(size_t)p * Ee];
    d_avg[b * Ee + e] = s * (1.0f / Pp);
}

// ---------------- embedding gather ----------------
__global__ void embGatherKer(const int* __restrict__ cap, const float* __restrict__ Wemb) {
    int i = blockIdx.x * 256 + threadIdx.x;
    if (i >= TS * Bb * Hh) return;
    int h = i % Hh;
    int r = i / Hh;
    int t = r / Bb;
    int b = r % Bb;
    int tok = cap[b * Tt + t];
    d_embMat[i] = Wemb[(size_t)tok * Hh + h];
}

// ---------------- tensor-core GEMM (3xtf32): out = A[M,K] @ W[K,N] ----------------
// CTA tile 128(M) x 64(N), K-step 16. 8 warps: 4 along M, 2 along N, each 32x32.
// grid = (ceil(N/64), KS, M/128). If KS>1: writes partials part[ks][128][N]
// (skinny case, M==128). If KS==1: writes out[(m0+r)*N + c] (+bias).
// Requires: M%128==0, kchunk%16==0, lda==K.
__global__ void __launch_bounds__(256) mma3Gemm(const float* __restrict__ A,
                                                const float* __restrict__ W,
                                                float* __restrict__ out,
                                                int K, int N, int ldw,
                                                int kchunk, int KS,
                                                const float* __restrict__ bias) {
    __shared__ __align__(16) float As[128][20];   // pad 16->20: conflict-free frag loads
    __shared__ __align__(16) float Bs[16][72];    // pad 64->72
    int t = threadIdx.x;
    int warp = t >> 5, lane = t & 31;
    int wm = (warp & 3) * 32;
    int wn = (warp >> 2) * 32;
    int n0 = blockIdx.x * 64;
    int ks = blockIdx.y;
    int m0 = blockIdx.z * 128;
    int kbeg = ks * kchunk, kend = kbeg + kchunk;
    int lq = lane >> 2;       // 0..7
    int lr = lane & 3;        // 0..3

    int arow = t >> 1, akq = (t & 1) * 8;
    int bkr = t >> 4, bnq = (t & 15) * 4;
    bool bvalid = (n0 + bnq) < N;

    float acc[2][4][4];
#pragma unroll
    for (int mi = 0; mi < 2; mi++)
#pragma unroll
        for (int ni = 0; ni < 4; ni++)
#pragma unroll
            for (int r = 0; r < 4; r++) acc[mi][ni][r] = 0.f;

    const float* aBase = A + (size_t)(m0 + arow) * K;

    for (int k0 = kbeg; k0 < kend; k0 += 16) {
        float4 a0 = *(const float4*)(aBase + k0 + akq);
        float4 a1 = *(const float4*)(aBase + k0 + akq + 4);
        float4 bv = make_float4(0.f, 0.f, 0.f, 0.f);
        if (bvalid) bv = *(const float4*)(W + (size_t)(k0 + bkr) * ldw + n0 + bnq);
        __syncthreads();
        *(float4*)&As[arow][akq] = a0;
        *(float4*)&As[arow][akq + 4] = a1;
        *(float4*)&Bs[bkr][bnq] = bv;
        __syncthreads();
#pragma unroll
        for (int kk = 0; kk < 16; kk += 8) {
            uint32_t Ahi[2][4], Alo[2][4];
#pragma unroll
            for (int mi = 0; mi < 2; mi++) {
                int rb = wm + mi * 16;
                float av0 = As[rb + lq][kk + lr];
                float av1 = As[rb + lq + 8][kk + lr];
                float av2 = As[rb + lq][kk + lr + 4];
                float av3 = As[rb + lq + 8][kk + lr + 4];
                split_tf32(av0, Ahi[mi][0], Alo[mi][0]);
                split_tf32(av1, Ahi[mi][1], Alo[mi][1]);
                split_tf32(av2, Ahi[mi][2], Alo[mi][2]);
                split_tf32(av3, Ahi[mi][3], Alo[mi][3]);
            }
            uint32_t Bhi[4][2], Blo[4][2];
#pragma unroll
            for (int ni = 0; ni < 4; ni++) {
                int cb = wn + ni * 8;
                float b0 = Bs[kk + lr][cb + lq];
                float b1 = Bs[kk + lr + 4][cb + lq];
                split_tf32(b0, Bhi[ni][0], Blo[ni][0]);
                split_tf32(b1, Bhi[ni][1], Blo[ni][1]);
            }
#pragma unroll
            for (int mi = 0; mi < 2; mi++)
#pragma unroll
                for (int ni = 0; ni < 4; ni++) {
                    mma_tf32(acc[mi][ni], Alo[mi], Bhi[ni]);
                    mma_tf32(acc[mi][ni], Ahi[mi], Blo[ni]);
                    mma_tf32(acc[mi][ni], Ahi[mi], Bhi[ni]);
                }
        }
    }

    float* dst = (KS > 1) ? (out + (size_t)ks * 128 * N) : out;
#pragma unroll
    for (int mi = 0; mi < 2; mi++) {
        int r0 = wm + mi * 16 + lq;
#pragma unroll
        for (int ni = 0; ni < 4; ni++) {
            int c = wn + ni * 8 + lr * 2;
            int gc = n0 + c;
            size_t rowA = (size_t)(m0 + r0) * N;
            size_t rowB = (size_t)(m0 + r0 + 8) * N;
            if (gc < N) {
                float b0 = bias ? bias[gc] : 0.f;
                dst[rowA + gc] = acc[mi][ni][0] + b0;
                dst[rowB + gc] = acc[mi][ni][2] + b0;
            }
            if (gc + 1 < N) {
                float b1 = bias ? bias[gc + 1] : 0.f;
                dst[rowA + gc + 1] = acc[mi][ni][1] + b1;
                dst[rowB + gc + 1] = acc[mi][ni][3] + b1;
            }
        }
    }
}

// ---------------- epilogues ----------------
__global__ void epiInitKer(int KS, const float* __restrict__ bih, const float* __restrict__ bic) {
    int i = blockIdx.x * 256 + threadIdx.x;
    if (i >= Bb * NINIT) return;
    int m = i / NINIT, n = i % NINIT;
    float s = 0.f;
    for (int ks = 0; ks < KS; ks++) s += d_part[(size_t)ks * Bb * NINIT + i];
    if (n < 512) d_h[m * Hh + n] = tanhf(s + bih[n]);
    else         d_c[m * Hh + (n - 512)] = tanhf(s + bic[n - 512]);
}

__global__ void epiPredsKer(int KS, const float* __restrict__ bdo,
                            float* __restrict__ outp, int t) {
    int i = blockIdx.x * 256 + threadIdx.x;
    if (i >= Bb * Vv) return;
    int m = i / Vv, n = i % Vv;
    float s = bdo[n];
    for (int ks = 0; ks < KS; ks++) s += d_part[(size_t)ks * Bb * Vv + i];
    outp[(size_t)m * TS * Vv + (size_t)t * Vv + n] = s;
}

__global__ void lstmFusedKer(int KS, const float* __restrict__ embWl_t,
                             const float* __restrict__ bl) {
    int i = blockIdx.x * 256 + threadIdx.x;
    if (i >= Bb * Hh) return;
    int m = i / Hh, n = i % Hh;
    float g[4];
#pragma unroll
    for (int j = 0; j < 4; j++) {
        int col = j * Hh + n;
        float s = bl[col] + embWl_t[m * G4 + col] + d_hcat[m * NCAT + 2560 + col];
        for (int ks = 0; ks < KS; ks++) s += d_part[(size_t)ks * Bb * G4 + m * G4 + col];
        g[j] = s;
    }
    float ig = sigf(g[0]);
    float fg = sigf(g[1]);
    float gg = tanhf(g[2]);
    float og = sigf(g[3]);
    float cc = fg * d_c[i] + ig * gg;
    d_c[i] = cc;
    d_h[i] = og * tanhf(cc);
}

// ---------------- attention: fused hcat-reduce + scores + softmax ----------------
__global__ void __launch_bounds__(256) attKer(const float* __restrict__ v_att,
                                              const float* __restrict__ bU,
                                              const float* __restrict__ bfb,
                                              float* __restrict__ alphasOut, int t) {
    int b = blockIdx.x, tid = threadIdx.x;
    __shared__ float hU[512];
    __shared__ float vv[512];
    __shared__ float e_sm[Pp];
    __shared__ float red[256];

    // fused epilogue of the hcat GEMM (KS=4): reduce partials, bias/activation
    for (int i = tid; i < NCAT; i += 256) {
        size_t idx = (size_t)b * NCAT + i;
        float s = d_part[idx] + d_part[(size_t)Bb * NCAT + idx]
                + d_part[2 * (size_t)Bb * NCAT + idx] + d_part[3 * (size_t)Bb * NCAT + idx];
        if (i < 512) {
            hU[i] = s + bU[i];
        } else if (i < 2560) {
            d_hcat[idx] = sigf(s + bfb[i - 512]);
        } else {
            d_hcat[idx] = s;
        }
    }
    vv[tid] = v_att[tid];
    vv[tid + 256] = v_att[tid + 256];
    __syncthreads();

    int w = tid >> 5, lane = tid & 31;
    for (int p = w; p < Pp; p += 8) {
        const float* ws = d_Ws + (size_t)(b * Pp + p) * Hh;
        float s = 0.f;
#pragma unroll
        for (int i = 0; i < 16; i++) {
            int hh = lane + 32 * i;
            s += tanhf(ws[hh] + hU[hh]) * vv[hh];
        }
#pragma unroll
        for (int o = 16; o; o >>= 1) s += __shfl_xor_sync(0xffffffffu, s, o);
        if (lane == 0) e_sm[p] = s;
    }
    __syncthreads();
    float mx = -1e30f;
    for (int p = tid; p < Pp; p += 256) mx = fmaxf(mx, e_sm[p]);
    red[tid] = mx;
    __syncthreads();
    for (int s2 = 128; s2 > 0; s2 >>= 1) {
        if (tid < s2) red[tid] = fmaxf(red[tid], red[tid + s2]);
        __syncthreads();
    }
    mx = red[0];
    __syncthreads();
    float sum = 0.f;
    for (int p = tid; p < Pp; p += 256) sum += expf(e_sm[p] - mx);
    red[tid] = sum;
    __syncthreads();
    for (int s2 = 128; s2 > 0; s2 >>= 1) {
        if (tid < s2) red[tid] += red[tid + s2];
        __syncthreads();
    }
    float inv = 1.0f / red[0];
    for (int p = tid; p < Pp; p += 256) {
        float a = expf(e_sm[p] - mx) * inv;
        d_alpha[b * Pp + p] = a;
        alphasOut[((size_t)b * TS + t) * Pp + p] = a;
    }
}

// ---------------- context = alpha @ F, gated ----------------
__global__ void __launch_bounds__(256) ctxKer(const float* __restrict__ F) {
    int b = blockIdx.y;
    int e = blockIdx.x * 256 + threadIdx.x;
    __shared__ float al[Pp];
    if (threadIdx.x < Pp) al[threadIdx.x] = d_alpha[b * Pp + threadIdx.x];
    __syncthreads();
    const float* f = F + (size_t)b * Pp * Ee + e;
    float s = 0.f;
#pragma unroll 7
    for (int p = 0; p < Pp; p++) s += al[p] * f[(size_t)p * Ee];
    float gate = d_hcat[b * NCAT + 512 + e];
    d_gctx[b * Ee + e] = s * gate;
}

// ---------------- host ----------------
extern "C" void kernel_launch(void* const* d_in, const int* in_sizes, int n_in,
                              void* d_out, int out_size) {
    const float* F      = (const float*)d_in[0];
    const int*   cap    = (const int*)d_in[1];
    const float* U_att  = (const float*)d_in[2];
    const float* bU_att = (const float*)d_in[3];
    const float* W_att  = (const float*)d_in[4];
    const float* bW_att = (const float*)d_in[5];
    const float* v_att  = (const float*)d_in[6];
    // d_in[7] = bv_att: constant shift before softmax — cancels exactly, unused.
    const float* Wih    = (const float*)d_in[8];
    const float* bih    = (const float*)d_in[9];
    const float* Wic    = (const float*)d_in[10];
    const float* bic    = (const float*)d_in[11];
    const float* Wfb    = (const float*)d_in[12];
    const float* bfb    = (const float*)d_in[13];
    const float* Wdo    = (const float*)d_in[14];
    const float* bdo    = (const float*)d_in[15];
    const float* Wemb   = (const float*)d_in[16];
    const float* Wl     = (const float*)d_in[17];
    const float* Ul     = (const float*)d_in[18];
    const float* bl     = (const float*)d_in[19];

    float* outp = (float*)d_out;
    float* alphasOut = outp + (size_t)Bb * TS * Vv;

    float *pPart, *pWcat, *pWcatI, *pAvg, *pH, *pGctx, *pEmbMat, *pEmbWl, *pWs;
    cudaGetSymbolAddress((void**)&pPart, d_part);
    cudaGetSymbolAddress((void**)&pWcat, d_Wcat);
    cudaGetSymbolAddress((void**)&pWcatI, d_WcatI);
    cudaGetSymbolAddress((void**)&pAvg, d_avg);
    cudaGetSymbolAddress((void**)&pH, d_h);
    cudaGetSymbolAddress((void**)&pGctx, d_gctx);
    cudaGetSymbolAddress((void**)&pEmbMat, d_embMat);
    cudaGetSymbolAddress((void**)&pEmbWl, d_embWl);
    cudaGetSymbolAddress((void**)&pWs, d_Ws);

    // ---- precompute ----
    buildWcatKer<<<(Hh * NCAT) / 256, 256>>>(U_att, Wfb, Ul);
    buildWcatIKer<<<(Ee * NINIT) / 256, 256>>>(Wih, Wic);
    avgKer<<<dim3(Ee / 256, Bb), 256>>>(F);
    // init state: [128,1024] = avg @ WcatI, split-K 8
    mma3Gemm<<<dim3(NINIT / 64, 8, 1), 256>>>(pAvg, pWcatI, pPart, Ee, NINIT, NINIT, Ee / 8, 8, nullptr);
    epiInitKer<<<(Bb * NINIT) / 256, 256>>>(8, bih, bic);
    // W_s = F2d[25088,2048] @ W_att[2048,512] + bW  (KS=1, direct+bias)
    mma3Gemm<<<dim3(Hh / 64, 1, (Bb * Pp) / 128), 256>>>(F, W_att, pWs, Ee, Hh, Hh, Ee, 1, bW_att);
    // embeddings then embWl = emb @ Wl_top (KS=1)
    embGatherKer<<<(TS * Bb * Hh) / 256, 256>>>(cap, Wemb);
    mma3Gemm<<<dim3(G4 / 64, 1, (TS * Bb) / 128), 256>>>(pEmbMat, Wl, pEmbWl, Hh, G4, G4, Hh, 1, nullptr);

    // ---- sequential decode ----
    for (int t = 0; t < TS; t++) {
        // h @ [U_att | Wfb | Ul]  (K=512, N=4608), split-K 4
        mma3Gemm<<<dim3(NCAT / 64, 4, 1), 256>>>(pH, pWcat, pPart, Hh, NCAT, NCAT, Hh / 4, 4, nullptr);
        // fused hcat-epilogue + attention + softmax
        attKer<<<Bb, 256>>>(v_att, bU_att, bfb, alphasOut, t);
        // gated context
        ctxKer<<<dim3(Ee / 256, Bb), 256>>>(F);
        // gates partial: gctx[128,2048] @ Wl_bot[2048,2048], split-K 8
        mma3Gemm<<<dim3(G4 / 64, 8, 1), 256>>>(pGctx, Wl + (size_t)Hh * G4, pPart, Ee, G4, G4, Ee / 8, 8, nullptr);
        // LSTM pointwise
        lstmFusedKer<<<(Bb * Hh) / 256, 256>>>(8, pEmbWl + (size_t)t * Bb * G4, bl);
        // preds: h_new[128,512] @ Wdo[512,10000], split-K 4
        mma3Gemm<<<dim3((Vv + 63) / 64, 4, 1), 256>>>(pH, Wdo, pPart, Hh, Vv, Vv, Hh / 4, 4, nullptr);
        epiPredsKer<<<(Bb * Vv) / 256, 256>>>(4, bdo, outp, t);
    }
}